// round 1
// baseline (speedup 1.0000x reference)
#include <cuda_runtime.h>
#include <cstdint>

// ---------------- configuration (fixed for this problem instance) ----------------
#define OUT_DIM   640           // = rep_dim = out_dim for METADATA [64,64,32,32]
#define NG        (OUT_DIM/32)  // 20 output groups of 32
#define ROWS      16            // batch rows per block
#define MAX_M     32768
#define MAX_B     (MAX_M/256)
#define ELL_ROWCAP 16384        // padded warp-iterations cap
#define ELL_CAP   (ELL_ROWCAP*32)

// ---------------- device scratch (no runtime allocation allowed) ----------------
__device__ int      d_rank[MAX_M];            // stable rank of term within its output segment (local part)
__device__ int      d_hist[MAX_B * OUT_DIM];  // per-256-block histogram -> exclusive block prefix
__device__ int      d_counts[OUT_DIM];        // total terms per output index
__device__ int      d_maxlen[NG];             // padded segment length per 32-output group
__device__ int      d_gbase[NG + 1];          // exclusive prefix of maxlen (warp-iteration base)
__device__ unsigned d_ell_idx[ELL_CAP];       // packed (r1 | r2<<16), [group][k][lane]
__device__ float    d_ell_cg[ELL_CAP];        // cg coefficient, same layout (0 = padding)

// ---------------- preprocessing kernels (run every launch; deterministic) ----------------

__global__ void k_zero(int histN) {
    int total = ELL_CAP;  // ELL_CAP >= histN always in practice, but guard both
    if (histN > total) total = histN;
    for (int i = blockIdx.x * blockDim.x + threadIdx.x; i < total;
         i += gridDim.x * blockDim.x) {
        if (i < histN) d_hist[i] = 0;
        if (i < ELL_CAP) { d_ell_idx[i] = 0u; d_ell_cg[i] = 0.0f; }
    }
}

// Per-256-element block: stable local rank + block histogram.
__global__ void k_rank(const int* __restrict__ ro, int M) {
    __shared__ int s_ro[256];
    int b = blockIdx.x, t = threadIdx.x;
    int m = b * 256 + t;
    int o = -1;
    if (m < M) o = ro[m];
    s_ro[t] = o;
    __syncthreads();
    if (m < M && o >= 0 && o < OUT_DIM) {
        int r = 0;
        for (int j = 0; j < t; j++) r += (s_ro[j] == o);
        d_rank[m] = r;
        atomicAdd(&d_hist[b * OUT_DIM + o], 1);
    }
}

// Column-wise exclusive prefix over blocks; totals -> d_counts.
__global__ void k_prefix(int B) {
    int o = blockIdx.x * blockDim.x + threadIdx.x;
    if (o < OUT_DIM) {
        int run = 0;
        for (int b = 0; b < B; b++) {
            int t = d_hist[b * OUT_DIM + o];
            d_hist[b * OUT_DIM + o] = run;
            run += t;
        }
        d_counts[o] = run;
    }
}

// One warp: per-group max length + exclusive prefix of group lengths.
__global__ void k_gmeta() {
    int lane = threadIdx.x;
    int base = 0;
    for (int og = 0; og < NG; og++) {
        int c = d_counts[og * 32 + lane];
        #pragma unroll
        for (int off = 16; off; off >>= 1)
            c = max(c, __shfl_xor_sync(0xFFFFFFFFu, c, off));
        // c is now the group max on all lanes
        if (base + c > ELL_ROWCAP) c = ELL_ROWCAP - base;  // safety clamp
        if (lane == 0) { d_maxlen[og] = c; d_gbase[og] = base; }
        base += c;
    }
    if (lane == 0) d_gbase[NG] = base;
}

// Scatter terms into grouped-ELL layout.
__global__ void k_scatter(const int* __restrict__ r1, const int* __restrict__ r2,
                          const int* __restrict__ ro, const float* __restrict__ cg,
                          int M) {
    int m = blockIdx.x * blockDim.x + threadIdx.x;
    if (m >= M) return;
    int o = ro[m];
    if (o < 0 || o >= OUT_DIM) return;
    int og = o >> 5, lane = o & 31;
    int b = m >> 8;
    int k = d_rank[m] + d_hist[b * OUT_DIM + o];
    long pos = ((long)(d_gbase[og] + k)) * 32 + lane;
    if (pos >= 0 && pos < ELL_CAP) {
        d_ell_idx[pos] = ((unsigned)r1[m] & 0xFFFFu) | (((unsigned)r2[m] & 0xFFFFu) << 16);
        d_ell_cg[pos]  = cg[m];
    }
}

// ---------------- main kernel ----------------
// Block: 256 threads (8 warps), ROWS=16 batch rows in smem.
// Each warp owns 2 rows; lanes = 32 outputs of the current group.
// Gathers are conflict-free LDS (consecutive lanes -> consecutive addresses),
// index loads are coalesced 128B and L1-resident, stores are coalesced.
__global__ __launch_bounds__(256) void k_main(const float* __restrict__ x1,
                                              const float* __restrict__ x2,
                                              float* __restrict__ out, int N) {
    extern __shared__ float sm[];
    float* x1s = sm;                   // [ROWS][640]
    float* x2s = sm + ROWS * OUT_DIM;  // [ROWS][640]

    int row0 = blockIdx.x * ROWS;
    int rows_here = N - row0;
    if (rows_here > ROWS) rows_here = ROWS;

    // cooperative coalesced load (float4)
    {
        const float4* g1 = (const float4*)(x1 + (size_t)row0 * OUT_DIM);
        const float4* g2 = (const float4*)(x2 + (size_t)row0 * OUT_DIM);
        float4* s1 = (float4*)x1s;
        float4* s2 = (float4*)x2s;
        int n4 = rows_here * (OUT_DIM / 4);
        for (int i = threadIdx.x; i < n4; i += blockDim.x) {
            s1[i] = g1[i];
            s2[i] = g2[i];
        }
    }
    __syncthreads();

    int wid = threadIdx.x >> 5, lane = threadIdx.x & 31;
    int r_local = wid * 2;
    bool has0 = (row0 + r_local) < N;
    bool has1 = (row0 + r_local + 1) < N;

    const float* a0 = x1s + r_local * OUT_DIM;
    const float* a1 = a0 + OUT_DIM;
    const float* b0 = x2s + r_local * OUT_DIM;
    const float* b1 = b0 + OUT_DIM;
    float* o0 = out + (size_t)(row0 + r_local) * OUT_DIM;

    for (int og = 0; og < NG; og++) {
        int base = d_gbase[og];
        int len  = d_maxlen[og];
        const unsigned* ip = d_ell_idx + (size_t)base * 32 + lane;
        const float*    cp = d_ell_cg  + (size_t)base * 32 + lane;
        float acc0 = 0.0f, acc1 = 0.0f;
        #pragma unroll 4
        for (int k = 0; k < len; k++) {
            unsigned p = ip[(size_t)k * 32];
            float    c = cp[(size_t)k * 32];
            int i1 = (int)(p & 0xFFFFu);
            int i2 = (int)(p >> 16);
            acc0 = fmaf(c * a0[i1], b0[i2], acc0);
            acc1 = fmaf(c * a1[i1], b1[i2], acc1);
        }
        int ocol = og * 32 + lane;
        if (has0) o0[ocol] = acc0;
        if (has1) o0[OUT_DIM + ocol] = acc1;
    }
}

// ---------------- launch ----------------
extern "C" void kernel_launch(void* const* d_in, const int* in_sizes, int n_in,
                              void* d_out, int out_size) {
    const float* x1 = (const float*)d_in[0];
    const float* x2 = (const float*)d_in[1];
    const float* cg = (const float*)d_in[2];
    const int*   r1 = (const int*)d_in[3];
    const int*   r2 = (const int*)d_in[4];
    const int*   ro = (const int*)d_in[5];

    int M = in_sizes[2];                 // number of sparse terms
    if (M > MAX_M) M = MAX_M;            // safety (expected M ~ 3.5K)
    int N = out_size / OUT_DIM;          // batch rows
    int B = (M + 255) / 256;

    k_zero<<<256, 256>>>(B * OUT_DIM);
    k_rank<<<B, 256>>>(ro, M);
    k_prefix<<<(OUT_DIM + 255) / 256, 256>>>(B);
    k_gmeta<<<1, 32>>>();
    k_scatter<<<B, 256>>>(r1, r2, ro, cg, M);

    size_t smem = (size_t)2 * ROWS * OUT_DIM * sizeof(float);  // 80 KB
    cudaFuncSetAttribute(k_main, cudaFuncAttributeMaxDynamicSharedMemorySize,
                         (int)smem);
    int nblocks = (N + ROWS - 1) / ROWS;
    k_main<<<nblocks, 256, smem>>>(x1, x2, (float*)d_out, N);
}